// round 2
// baseline (speedup 1.0000x reference)
#include <cuda_runtime.h>

#define NN 100000
#define EE 800000
#define DD 64

// Scratch (allocation-free rule: __device__ globals)
__device__ float g_xt[NN * DD];     // x-tilde = dis_v * (sum dis_u * x_u + dis_v * x_v)
__device__ float g_x[NN * DD];      // ping-pong x between rounds
__device__ int   g_deg[NN];
__device__ int   g_rowptr[NN + 1];
__device__ int   g_cursor[NN];
__device__ int   g_col[EE];
__device__ float g_dis[NN];

// ---------------- CSR build ----------------

__global__ void k_hist(const int* __restrict__ dst, int e) {
    int i = blockIdx.x * blockDim.x + threadIdx.x;
    if (i < e) atomicAdd(&g_deg[dst[i]], 1);
}

// Single-block exclusive scan over deg -> rowptr/cursor; also dis = rsqrt(deg+1)
__global__ void k_scan(int n) {
    __shared__ int part[1024];
    int t = threadIdx.x;
    int C = (n + 1023) / 1024;
    int lo = t * C;
    int hi = min(lo + C, n);
    int s = 0;
    for (int i = lo; i < hi; i++) s += g_deg[i];
    part[t] = s;
    __syncthreads();
    for (int off = 1; off < 1024; off <<= 1) {
        int v = (t >= off) ? part[t - off] : 0;
        __syncthreads();
        part[t] += v;
        __syncthreads();
    }
    int run = (t == 0) ? 0 : part[t - 1];
    for (int i = lo; i < hi; i++) {
        int d = g_deg[i];
        g_rowptr[i] = run;
        g_cursor[i] = run;
        g_dis[i] = rsqrtf((float)(d + 1));   // +1 self-loop
        run += d;
    }
    if (t == 1023) g_rowptr[n] = run;
}

__global__ void k_scatter(const int* __restrict__ src, const int* __restrict__ dst, int e) {
    int i = blockIdx.x * blockDim.x + threadIdx.x;
    if (i < e) {
        int d = dst[i];
        int pos = atomicAdd(&g_cursor[d], 1);
        g_col[pos] = src[i];
    }
}

// ---------------- per-round kernels ----------------

// One warp per node v:
//   xt[v] = dis_v * ( sum_{u->v} dis_u * x[u]  +  dis_v * x[v] )
__global__ __launch_bounds__(256) void k_agg(const float* __restrict__ xin,
                                             float* __restrict__ xt, int n) {
    int wid  = (blockIdx.x * blockDim.x + threadIdx.x) >> 5;
    int lane = threadIdx.x & 31;
    if (wid >= n) return;
    int v = wid;

    const float2* x2 = (const float2*)xin;
    float dv = g_dis[v];
    float2 self = x2[(size_t)v * 32 + lane];
    float2 acc;
    acc.x = dv * self.x;
    acc.y = dv * self.y;

    int rp0 = g_rowptr[v];
    int rp1 = g_rowptr[v + 1];
    for (int base = rp0; base < rp1; base += 32) {
        int j = base + lane;
        int c = 0;
        float du = 0.f;
        if (j < rp1) { c = g_col[j]; du = g_dis[c]; }
        int cnt = min(32, rp1 - base);
        int jj = 0;
        for (; jj + 4 <= cnt; jj += 4) {
            int u0 = __shfl_sync(0xffffffffu, c, jj + 0);
            int u1 = __shfl_sync(0xffffffffu, c, jj + 1);
            int u2 = __shfl_sync(0xffffffffu, c, jj + 2);
            int u3 = __shfl_sync(0xffffffffu, c, jj + 3);
            float d0 = __shfl_sync(0xffffffffu, du, jj + 0);
            float d1 = __shfl_sync(0xffffffffu, du, jj + 1);
            float d2 = __shfl_sync(0xffffffffu, du, jj + 2);
            float d3 = __shfl_sync(0xffffffffu, du, jj + 3);
            float2 m0 = x2[(size_t)u0 * 32 + lane];
            float2 m1 = x2[(size_t)u1 * 32 + lane];
            float2 m2 = x2[(size_t)u2 * 32 + lane];
            float2 m3 = x2[(size_t)u3 * 32 + lane];
            acc.x += d0 * m0.x; acc.y += d0 * m0.y;
            acc.x += d1 * m1.x; acc.y += d1 * m1.y;
            acc.x += d2 * m2.x; acc.y += d2 * m2.y;
            acc.x += d3 * m3.x; acc.y += d3 * m3.y;
        }
        for (; jj < cnt; jj++) {
            int   u = __shfl_sync(0xffffffffu, c, jj);
            float d = __shfl_sync(0xffffffffu, du, jj);
            float2 m = x2[(size_t)u * 32 + lane];
            acc.x += d * m.x;
            acc.y += d * m.y;
        }
    }

    acc.x *= dv;
    acc.y *= dv;
    ((float2*)xt)[(size_t)v * 32 + lane] = acc;
}

// Fused: out = LayerNorm( xt @ W + b ) * gamma + beta
// Block: 64 rows x 64 cols, 256 threads, each 4x4 outputs. LN via 16-lane shfl.
__global__ __launch_bounds__(256) void k_gemm_ln(const float* __restrict__ xt,
                                                 const float* __restrict__ W,
                                                 const float* __restrict__ b,
                                                 const float* __restrict__ gamma,
                                                 const float* __restrict__ beta,
                                                 float* __restrict__ out, int n) {
    __shared__ float Wsh[DD * DD];      // [k][c]
    __shared__ float Xsh[DD * DD];      // [r][k]

    int t = threadIdx.x;
    int rowbase = blockIdx.x * 64;

    {
        const float4* W4 = (const float4*)W;
        float4* Ws4 = (float4*)Wsh;
        #pragma unroll
        for (int i = t; i < 1024; i += 256) Ws4[i] = W4[i];
    }
    {
        float4* Xs4 = (float4*)Xsh;
        #pragma unroll
        for (int i = t; i < 1024; i += 256) {
            int r = i >> 4, k4 = i & 15;
            float4 v = make_float4(0.f, 0.f, 0.f, 0.f);
            if (rowbase + r < n)
                v = ((const float4*)(xt + (size_t)(rowbase + r) * DD))[k4];
            Xs4[i] = v;
        }
    }
    __syncthreads();

    int tx = t & 15;        // cols tx*4 .. tx*4+3
    int ty = t >> 4;        // rows ty*4 .. ty*4+3

    float acc[4][4];
    #pragma unroll
    for (int i = 0; i < 4; i++)
        #pragma unroll
        for (int j = 0; j < 4; j++) acc[i][j] = 0.f;

    #pragma unroll 8
    for (int k = 0; k < 64; k++) {
        float4 w = ((const float4*)(Wsh + k * DD))[tx];
        float a0 = Xsh[(ty * 4 + 0) * DD + k];
        float a1 = Xsh[(ty * 4 + 1) * DD + k];
        float a2 = Xsh[(ty * 4 + 2) * DD + k];
        float a3 = Xsh[(ty * 4 + 3) * DD + k];
        acc[0][0] += a0 * w.x; acc[0][1] += a0 * w.y; acc[0][2] += a0 * w.z; acc[0][3] += a0 * w.w;
        acc[1][0] += a1 * w.x; acc[1][1] += a1 * w.y; acc[1][2] += a1 * w.z; acc[1][3] += a1 * w.w;
        acc[2][0] += a2 * w.x; acc[2][1] += a2 * w.y; acc[2][2] += a2 * w.z; acc[2][3] += a2 * w.w;
        acc[3][0] += a3 * w.x; acc[3][1] += a3 * w.y; acc[3][2] += a3 * w.z; acc[3][3] += a3 * w.w;
    }

    // bias
    float4 bb = ((const float4*)b)[tx];
    #pragma unroll
    for (int i = 0; i < 4; i++) {
        acc[i][0] += bb.x; acc[i][1] += bb.y; acc[i][2] += bb.z; acc[i][3] += bb.w;
    }

    // Row LayerNorm: reduce across the 16 tx lanes (same 16-lane shfl group)
    float s[4], ss[4];
    #pragma unroll
    for (int i = 0; i < 4; i++) {
        s[i]  = acc[i][0] + acc[i][1] + acc[i][2] + acc[i][3];
        ss[i] = acc[i][0] * acc[i][0] + acc[i][1] * acc[i][1]
              + acc[i][2] * acc[i][2] + acc[i][3] * acc[i][3];
    }
    #pragma unroll
    for (int o = 8; o > 0; o >>= 1) {
        #pragma unroll
        for (int i = 0; i < 4; i++) {
            s[i]  += __shfl_xor_sync(0xffffffffu, s[i],  o);
            ss[i] += __shfl_xor_sync(0xffffffffu, ss[i], o);
        }
    }

    float4 gm = ((const float4*)gamma)[tx];
    float4 bt = ((const float4*)beta)[tx];

    #pragma unroll
    for (int i = 0; i < 4; i++) {
        int r = rowbase + ty * 4 + i;
        if (r < n) {
            float mu  = s[i] * (1.f / 64.f);
            float var = ss[i] * (1.f / 64.f) - mu * mu;
            float inv = rsqrtf(var + 1e-5f);
            float4 o;
            o.x = (acc[i][0] - mu) * inv * gm.x + bt.x;
            o.y = (acc[i][1] - mu) * inv * gm.y + bt.y;
            o.z = (acc[i][2] - mu) * inv * gm.z + bt.z;
            o.w = (acc[i][3] - mu) * inv * gm.w + bt.w;
            ((float4*)(out + (size_t)r * DD))[tx] = o;
        }
    }
}

// ---------------- launch ----------------

extern "C" void kernel_launch(void* const* d_in, const int* in_sizes, int n_in,
                              void* d_out, int out_size) {
    const float* x     = (const float*)d_in[0];
    const int*   ei    = (const int*)d_in[1];
    const float* W     = (const float*)d_in[2];
    const float* b     = (const float*)d_in[3];
    const float* gamma = (const float*)d_in[4];
    const float* beta  = (const float*)d_in[5];

    int n = in_sizes[0] / DD;      // 100000
    int e = in_sizes[1] / 2;       // 800000
    const int* src = ei;
    const int* dst = ei + e;

    void* deg_ptr = nullptr;
    cudaGetSymbolAddress(&deg_ptr, g_deg);
    cudaMemsetAsync(deg_ptr, 0, (size_t)n * sizeof(int));

    k_hist<<<(e + 255) / 256, 256>>>(dst, e);
    k_scan<<<1, 1024>>>(n);
    k_scatter<<<(e + 255) / 256, 256>>>(src, dst, e);

    int gemm_blocks = (n + 63) / 64;
    int agg_blocks  = (n + 7) / 8;   // 8 warps / 256-thread block

    const int NUM_ROUNDS = 4;
    for (int r = 0; r < NUM_ROUNDS; r++) {
        const float* xin = (r == 0) ? x : (const float*)g_x;
        float* xout = (r == NUM_ROUNDS - 1) ? (float*)d_out : g_x;
        k_agg<<<agg_blocks, 256>>>(xin, (float*)g_xt, n);
        k_gemm_ln<<<gemm_blocks, 256>>>((const float*)g_xt, W, b, gamma, beta, xout, n);
    }
}

// round 4
// speedup vs baseline: 4.1127x; 4.1127x over previous
#include <cuda_runtime.h>

#define NN 100000
#define EE 800000
#define DD 64

// Scratch (allocation-free rule: __device__ globals)
__device__ float g_g[NN * DD];      // g = dis * (x @ W)
__device__ float g_x[NN * DD];      // ping-pong x between rounds
__device__ int   g_deg[NN];
__device__ int   g_rowptr[NN + 1];
__device__ int   g_cursor[NN];
__device__ int   g_col[EE];
__device__ float g_dis[NN];

// ---------------- CSR build ----------------

__global__ void k_hist(const int* __restrict__ dst, int e) {
    int i = blockIdx.x * blockDim.x + threadIdx.x;
    if (i < e) atomicAdd(&g_deg[dst[i]], 1);
}

// Single-block exclusive scan over deg -> rowptr/cursor; also dis = rsqrt(deg+1)
__global__ void k_scan(int n) {
    __shared__ int part[1024];
    int t = threadIdx.x;
    int C = (n + 1023) / 1024;
    int lo = t * C;
    int hi = min(lo + C, n);
    int s = 0;
    for (int i = lo; i < hi; i++) s += g_deg[i];
    part[t] = s;
    __syncthreads();
    for (int off = 1; off < 1024; off <<= 1) {
        int v = (t >= off) ? part[t - off] : 0;
        __syncthreads();
        part[t] += v;
        __syncthreads();
    }
    int run = (t == 0) ? 0 : part[t - 1];
    for (int i = lo; i < hi; i++) {
        int d = g_deg[i];
        g_rowptr[i] = run;
        g_cursor[i] = run;
        g_dis[i] = rsqrtf((float)(d + 1));   // +1 self-loop
        run += d;
    }
    if (t == 1023) g_rowptr[n] = run;
}

__global__ void k_scatter(const int* __restrict__ src, const int* __restrict__ dst, int e) {
    int i = blockIdx.x * blockDim.x + threadIdx.x;
    if (i < e) {
        int d = dst[i];
        int pos = atomicAdd(&g_cursor[d], 1);
        g_col[pos] = src[i];
    }
}

// ---------------- per-round kernels ----------------

// g = dis[r] * (x @ W).  Block computes a 64x64 tile. 256 threads, 4x4 outputs each.
__global__ __launch_bounds__(256) void k_gemm(const float* __restrict__ x,
                                              const float* __restrict__ W, int n) {
    __shared__ float Wsh[DD * DD];      // [k][c]
    __shared__ float Xsh[DD * DD];      // [r][k]

    int t = threadIdx.x;
    int rowbase = blockIdx.x * 64;

    {
        const float4* W4 = (const float4*)W;
        float4* Ws4 = (float4*)Wsh;
        #pragma unroll
        for (int i = t; i < 1024; i += 256) Ws4[i] = W4[i];
    }
    {
        float4* Xs4 = (float4*)Xsh;
        #pragma unroll
        for (int i = t; i < 1024; i += 256) {
            int r = i >> 4, k4 = i & 15;
            float4 v = make_float4(0.f, 0.f, 0.f, 0.f);
            if (rowbase + r < n)
                v = ((const float4*)(x + (size_t)(rowbase + r) * DD))[k4];
            Xs4[i] = v;
        }
    }
    __syncthreads();

    int tx = t & 15;        // cols tx*4 .. tx*4+3
    int ty = t >> 4;        // rows ty*4 .. ty*4+3

    float acc[4][4];
    #pragma unroll
    for (int i = 0; i < 4; i++)
        #pragma unroll
        for (int j = 0; j < 4; j++) acc[i][j] = 0.f;

    #pragma unroll 8
    for (int k = 0; k < 64; k++) {
        float4 w = ((const float4*)(Wsh + k * DD))[tx];
        float a0 = Xsh[(ty * 4 + 0) * DD + k];
        float a1 = Xsh[(ty * 4 + 1) * DD + k];
        float a2 = Xsh[(ty * 4 + 2) * DD + k];
        float a3 = Xsh[(ty * 4 + 3) * DD + k];
        acc[0][0] += a0 * w.x; acc[0][1] += a0 * w.y; acc[0][2] += a0 * w.z; acc[0][3] += a0 * w.w;
        acc[1][0] += a1 * w.x; acc[1][1] += a1 * w.y; acc[1][2] += a1 * w.z; acc[1][3] += a1 * w.w;
        acc[2][0] += a2 * w.x; acc[2][1] += a2 * w.y; acc[2][2] += a2 * w.z; acc[2][3] += a2 * w.w;
        acc[3][0] += a3 * w.x; acc[3][1] += a3 * w.y; acc[3][2] += a3 * w.z; acc[3][3] += a3 * w.w;
    }

    #pragma unroll
    for (int i = 0; i < 4; i++) {
        int r = rowbase + ty * 4 + i;
        if (r < n) {
            float d = g_dis[r];
            float4 o = make_float4(acc[i][0] * d, acc[i][1] * d, acc[i][2] * d, acc[i][3] * d);
            ((float4*)(g_g + (size_t)r * DD))[tx] = o;
        }
    }
}

// Two nodes per warp (16-lane halves, float4 per lane). Halves diverge
// (different edge counts) so ALL shuffles use per-half masks.
//   agg[v] = dis[v] * (sum_{u->v} g[u] + g[v]) + b, then LayerNorm -> out
__global__ __launch_bounds__(256) void k_agg_ln(const float* __restrict__ b,
                                                const float* __restrict__ gamma,
                                                const float* __restrict__ beta,
                                                float* __restrict__ out, int n) {
    int wid    = (blockIdx.x * blockDim.x + threadIdx.x) >> 5;
    int lane   = threadIdx.x & 31;
    int half   = lane >> 4;          // 0 or 1
    int lane16 = lane & 15;
    unsigned hmask = half ? 0xFFFF0000u : 0x0000FFFFu;

    int node = wid * 2 + half;
    if (wid * 2 >= n) return;        // whole warp out of range together
    int v = min(node, n - 1);        // clamp odd tail; store guarded below

    const float4* g4 = (const float4*)g_g;
    float4 acc = g4[(size_t)v * 16 + lane16];   // self-loop g[v]

    int rp0 = g_rowptr[v];
    int rp1 = g_rowptr[v + 1];
    int srcbase = half * 16;
    for (int base = rp0; base < rp1; base += 16) {
        int j = base + lane16;
        int c = (j < rp1) ? g_col[j] : 0;
        int cnt = min(16, rp1 - base);
        int jj = 0;
        for (; jj + 4 <= cnt; jj += 4) {
            int u0 = __shfl_sync(hmask, c, srcbase + jj + 0);
            int u1 = __shfl_sync(hmask, c, srcbase + jj + 1);
            int u2 = __shfl_sync(hmask, c, srcbase + jj + 2);
            int u3 = __shfl_sync(hmask, c, srcbase + jj + 3);
            float4 m0 = g4[(size_t)u0 * 16 + lane16];
            float4 m1 = g4[(size_t)u1 * 16 + lane16];
            float4 m2 = g4[(size_t)u2 * 16 + lane16];
            float4 m3 = g4[(size_t)u3 * 16 + lane16];
            acc.x += m0.x + m1.x + m2.x + m3.x;
            acc.y += m0.y + m1.y + m2.y + m3.y;
            acc.z += m0.z + m1.z + m2.z + m3.z;
            acc.w += m0.w + m1.w + m2.w + m3.w;
        }
        for (; jj < cnt; jj++) {
            int u = __shfl_sync(hmask, c, srcbase + jj);
            float4 m = g4[(size_t)u * 16 + lane16];
            acc.x += m.x; acc.y += m.y; acc.z += m.z; acc.w += m.w;
        }
    }

    float dv = g_dis[v];
    float4 bb = ((const float4*)b)[lane16];
    float a0 = acc.x * dv + bb.x;
    float a1 = acc.y * dv + bb.y;
    float a2 = acc.z * dv + bb.z;
    float a3 = acc.w * dv + bb.w;

    // LayerNorm over 64 features (4 per lane, 16 lanes; xor stays within half)
    float s  = a0 + a1 + a2 + a3;
    float ss = a0 * a0 + a1 * a1 + a2 * a2 + a3 * a3;
    #pragma unroll
    for (int o = 8; o > 0; o >>= 1) {
        s  += __shfl_xor_sync(hmask, s, o);
        ss += __shfl_xor_sync(hmask, ss, o);
    }
    float mu  = s * (1.f / 64.f);
    float var = ss * (1.f / 64.f) - mu * mu;
    float inv = rsqrtf(var + 1e-5f);

    float4 gm = ((const float4*)gamma)[lane16];
    float4 bt = ((const float4*)beta)[lane16];
    float4 o4;
    o4.x = (a0 - mu) * inv * gm.x + bt.x;
    o4.y = (a1 - mu) * inv * gm.y + bt.y;
    o4.z = (a2 - mu) * inv * gm.z + bt.z;
    o4.w = (a3 - mu) * inv * gm.w + bt.w;
    if (node < n)
        ((float4*)out)[(size_t)node * 16 + lane16] = o4;
}

// ---------------- launch ----------------

extern "C" void kernel_launch(void* const* d_in, const int* in_sizes, int n_in,
                              void* d_out, int out_size) {
    const float* x     = (const float*)d_in[0];
    const int*   ei    = (const int*)d_in[1];
    const float* W     = (const float*)d_in[2];
    const float* b     = (const float*)d_in[3];
    const float* gamma = (const float*)d_in[4];
    const float* beta  = (const float*)d_in[5];

    int n = in_sizes[0] / DD;      // 100000
    int e = in_sizes[1] / 2;       // 800000
    const int* src = ei;
    const int* dst = ei + e;

    void* deg_ptr = nullptr;
    cudaGetSymbolAddress(&deg_ptr, g_deg);
    cudaMemsetAsync(deg_ptr, 0, (size_t)n * sizeof(int));

    k_hist<<<(e + 255) / 256, 256>>>(dst, e);          // kernel 1
    k_scan<<<1, 1024>>>(n);                            // kernel 2
    k_scatter<<<(e + 255) / 256, 256>>>(src, dst, e);  // kernel 3

    int gemm_blocks = (n + 63) / 64;
    int warps       = (n + 1) / 2;
    int agg_blocks  = (warps + 7) / 8;   // 8 warps / 256-thread block

    const int NUM_ROUNDS = 4;
    for (int r = 0; r < NUM_ROUNDS; r++) {
        const float* xin = (r == 0) ? x : (const float*)g_x;
        float* xout = (r == NUM_ROUNDS - 1) ? (float*)d_out : g_x;
        k_gemm<<<gemm_blocks, 256>>>(xin, W, n);            // kernel 4 on r=0 -> profiled
        k_agg_ln<<<agg_blocks, 256>>>(b, gamma, beta, xout, n);
    }
}